// round 2
// baseline (speedup 1.0000x reference)
#include <cuda_runtime.h>
#include <stdint.h>

#define N_STRUCT   1000
#define ATOMS      100
#define N_SAMP     100000
#define N_GRAD     500000
#define DFEAT      128
#define NSEG       (N_STRUCT * ATOMS)      // 100000 dense (structure,atom) segments
#define ROW_F4     96                      // 3*128 floats / 4
#define GRAD_OUT_OFFSET (N_STRUCT * DFEAT) // 128000 floats

// -------- scratch (device globals; no runtime allocation) -----------------
__device__ int g_count[NSEG];        // per-segment degree
__device__ int g_start[NSEG + 1];    // CSR row offsets
__device__ int g_cursor[NSEG];       // scatter cursors
__device__ int g_rows[N_GRAD];       // CSR row-id list
__device__ int g_seg[N_GRAD];        // cached segment id per grad row

// ---------------------------------------------------------------------------
__global__ void zero_counts_kernel() {
    int i = blockIdx.x * blockDim.x + threadIdx.x;
    if (i < NSEG) g_count[i] = 0;
}

// count degrees + cache segment ids
__global__ void count_kernel(const int* __restrict__ gstruct,
                             const int* __restrict__ gatom) {
    int i = blockIdx.x * blockDim.x + threadIdx.x;
    if (i < N_GRAD) {
        int seg = gstruct[i] * ATOMS + gatom[i];
        g_seg[i] = seg;
        atomicAdd(&g_count[seg], 1);
    }
}

// single-block exclusive scan over NSEG counts (each thread owns a chunk)
__global__ void scan_kernel() {
    const int T = 1024;
    const int per = (NSEG + T - 1) / T;   // 98
    int tid = threadIdx.x;
    int start = tid * per;
    int end   = min(start + per, NSEG);

    int sum = 0;
    for (int r = start; r < end; ++r) sum += g_count[r];

    __shared__ int sh[T];
    sh[tid] = sum;
    __syncthreads();
    for (int off = 1; off < T; off <<= 1) {
        int v = (tid >= off) ? sh[tid - off] : 0;
        __syncthreads();
        if (tid >= off) sh[tid] += v;
        __syncthreads();
    }
    int run = (tid > 0) ? sh[tid - 1] : 0;   // exclusive prefix
    for (int r = start; r < end; ++r) {
        int c = g_count[r];
        g_start[r]  = run;
        g_cursor[r] = run;
        run += c;
    }
    if (tid == 0) g_start[NSEG] = N_GRAD;
}

// scatter row ids into CSR lists
__global__ void scatter_kernel() {
    int i = blockIdx.x * blockDim.x + threadIdx.x;
    if (i < N_GRAD) {
        int seg = g_seg[i];
        int pos = atomicAdd(&g_cursor[seg], 1);
        g_rows[pos] = i;
    }
}

// ---------------------------------------------------------------------------
// Per-structure sum of value rows (structure_ids sorted -> binary search).
// ---------------------------------------------------------------------------
__global__ void values_kernel(const float* __restrict__ values,
                              const int*   __restrict__ sid,
                              float*       __restrict__ out) {
    int s = blockIdx.x;
    int d = threadIdx.x;

    __shared__ int s_lo, s_hi;
    if (threadIdx.x == 0) {
        int lo = 0, hi = N_SAMP;
        while (lo < hi) { int m = (lo + hi) >> 1; if (sid[m] < s) lo = m + 1; else hi = m; }
        s_lo = lo;
        lo = s_lo; hi = N_SAMP;
        while (lo < hi) { int m = (lo + hi) >> 1; if (sid[m] < s + 1) lo = m + 1; else hi = m; }
        s_hi = lo;
    }
    __syncthreads();

    float acc = 0.f;
    for (int r = s_lo; r < s_hi; ++r)
        acc += values[(long long)r * DFEAT + d];
    out[(long long)s * DFEAT + d] = acc;
}

// ---------------------------------------------------------------------------
// Gather-reduce: one warp per segment. Each lane owns 3 float4 of the 1536B
// output row (lane, lane+32, lane+64). Streams source rows (coalesced 512B
// transactions), sums in registers, writes once. No atomics, no zero pass.
// ---------------------------------------------------------------------------
__global__ void gather_kernel(const float4* __restrict__ grad4,
                              float*        __restrict__ out_grad) {
    int warp_id = (blockIdx.x * blockDim.x + threadIdx.x) >> 5;
    int lane    = threadIdx.x & 31;
    if (warp_id >= NSEG) return;

    int lo = g_start[warp_id];
    int hi = g_start[warp_id + 1];

    float4 a0 = make_float4(0.f, 0.f, 0.f, 0.f);
    float4 a1 = a0, a2 = a0;

    for (int p = lo; p < hi; ++p) {
        const float4* src = grad4 + (long long)g_rows[p] * ROW_F4;
        float4 v0 = __ldcs(src + lane);
        float4 v1 = __ldcs(src + lane + 32);
        float4 v2 = __ldcs(src + lane + 64);
        a0.x += v0.x; a0.y += v0.y; a0.z += v0.z; a0.w += v0.w;
        a1.x += v1.x; a1.y += v1.y; a1.z += v1.z; a1.w += v1.w;
        a2.x += v2.x; a2.y += v2.y; a2.z += v2.z; a2.w += v2.w;
    }

    float4* dst = (float4*)(out_grad + (long long)warp_id * (3 * DFEAT));
    dst[lane]      = a0;
    dst[lane + 32] = a1;
    dst[lane + 64] = a2;
}

// ---------------------------------------------------------------------------
extern "C" void kernel_launch(void* const* d_in, const int* in_sizes, int n_in,
                              void* d_out, int out_size) {
    const float*  values  = (const float*)d_in[0];
    const int*    sid     = (const int*)  d_in[1];
    const float4* grad4   = (const float4*)d_in[2];
    const int*    gstruct = (const int*)  d_in[3];
    const int*    gatom   = (const int*)  d_in[4];

    float* out      = (float*)d_out;
    float* out_grad = out + GRAD_OUT_OFFSET;

    // CSR build
    zero_counts_kernel<<<(NSEG + 255) / 256, 256>>>();
    count_kernel<<<(N_GRAD + 255) / 256, 256>>>(gstruct, gatom);
    scan_kernel<<<1, 1024>>>();
    scatter_kernel<<<(N_GRAD + 255) / 256, 256>>>();

    // values segment-sum (independent; cheap)
    values_kernel<<<N_STRUCT, DFEAT>>>(values, sid, out);

    // gather-reduce: 100k warps, 8 warps/block
    {
        int threads = 256;
        int blocks  = (NSEG * 32 + threads - 1) / threads;   // 12500
        gather_kernel<<<blocks, threads>>>(grad4, out_grad);
    }
}

// round 3
// speedup vs baseline: 1.7548x; 1.7548x over previous
#include <cuda_runtime.h>
#include <stdint.h>

#define N_STRUCT   1000
#define ATOMS      100
#define N_SAMP     100000
#define N_GRAD     500000
#define DFEAT      128
#define NSEG       (N_STRUCT * ATOMS)      // 100000
#define ROW_F4     96                      // 3*128/4
#define GRAD_OUT_OFFSET (N_STRUCT * DFEAT)

#define SCAN_TILE  1024
#define SCAN_NB    ((NSEG + SCAN_TILE - 1) / SCAN_TILE)   // 98

// -------- scratch (device globals) -----------------------------------------
__device__ int g_count[NSEG];
__device__ int g_start[NSEG + 1];
__device__ int g_cursor[NSEG];
__device__ int g_rows[N_GRAD];
__device__ int g_seg[N_GRAD];
__device__ int g_bsum[SCAN_NB];
__device__ int g_boff[SCAN_NB];

// ---------------------------------------------------------------------------
__global__ void zero_counts_kernel() {
    int i = blockIdx.x * blockDim.x + threadIdx.x;
    if (i < NSEG) g_count[i] = 0;
}

__global__ void count_kernel(const int* __restrict__ gstruct,
                             const int* __restrict__ gatom) {
    int i = blockIdx.x * blockDim.x + threadIdx.x;
    if (i < N_GRAD) {
        int seg = gstruct[i] * ATOMS + gatom[i];
        g_seg[i] = seg;
        atomicAdd(&g_count[seg], 1);
    }
}

// Phase 1: per-tile sums (coalesced)
__global__ void scan_p1() {
    __shared__ int sh[SCAN_TILE];
    int b = blockIdx.x;
    int i = b * SCAN_TILE + threadIdx.x;
    int v = (i < NSEG) ? g_count[i] : 0;
    sh[threadIdx.x] = v;
    __syncthreads();
    for (int off = SCAN_TILE / 2; off > 0; off >>= 1) {
        if (threadIdx.x < off) sh[threadIdx.x] += sh[threadIdx.x + off];
        __syncthreads();
    }
    if (threadIdx.x == 0) g_bsum[b] = sh[0];
}

// Phase 2: exclusive scan of 98 tile sums (one block)
__global__ void scan_p2() {
    __shared__ int sh[128];
    int tid = threadIdx.x;
    int v = (tid < SCAN_NB) ? g_bsum[tid] : 0;
    sh[tid] = v;
    __syncthreads();
    for (int off = 1; off < 128; off <<= 1) {
        int t = (tid >= off) ? sh[tid - off] : 0;
        __syncthreads();
        sh[tid] += t;
        __syncthreads();
    }
    if (tid < SCAN_NB) g_boff[tid] = sh[tid] - v;   // exclusive
}

// Phase 3: tile-local exclusive scan + block offset; write g_start/g_cursor
__global__ void scan_p3() {
    __shared__ int sh[SCAN_TILE];
    int b = blockIdx.x;
    int i = b * SCAN_TILE + threadIdx.x;
    int v = (i < NSEG) ? g_count[i] : 0;
    sh[threadIdx.x] = v;
    __syncthreads();
    // Hillis-Steele inclusive scan
    for (int off = 1; off < SCAN_TILE; off <<= 1) {
        int t = (threadIdx.x >= off) ? sh[threadIdx.x - off] : 0;
        __syncthreads();
        sh[threadIdx.x] += t;
        __syncthreads();
    }
    if (i < NSEG) {
        int excl = sh[threadIdx.x] - v + g_boff[b];
        g_start[i]  = excl;
        g_cursor[i] = excl;
    }
    if (i == NSEG - 1) g_start[NSEG] = N_GRAD;
}

__global__ void scatter_kernel() {
    int i = blockIdx.x * blockDim.x + threadIdx.x;
    if (i < N_GRAD) {
        int pos = atomicAdd(&g_cursor[g_seg[i]], 1);
        g_rows[pos] = i;
    }
}

// ---------------------------------------------------------------------------
__global__ void values_kernel(const float* __restrict__ values,
                              const int*   __restrict__ sid,
                              float*       __restrict__ out) {
    int s = blockIdx.x;
    int d = threadIdx.x;

    __shared__ int s_lo, s_hi;
    if (threadIdx.x == 0) {
        int lo = 0, hi = N_SAMP;
        while (lo < hi) { int m = (lo + hi) >> 1; if (sid[m] < s) lo = m + 1; else hi = m; }
        s_lo = lo;
        lo = s_lo; hi = N_SAMP;
        while (lo < hi) { int m = (lo + hi) >> 1; if (sid[m] < s + 1) lo = m + 1; else hi = m; }
        s_hi = lo;
    }
    __syncthreads();

    float acc = 0.f;
    for (int r = s_lo; r < s_hi; ++r)
        acc += values[(long long)r * DFEAT + d];
    out[(long long)s * DFEAT + d] = acc;
}

// ---------------------------------------------------------------------------
// Gather-reduce, warp per segment. Row ids prefetched into lane registers and
// broadcast by shfl -> every source load is address-ready immediately (MLP ~3*cnt).
// ---------------------------------------------------------------------------
__global__ void gather_kernel(const float4* __restrict__ grad4,
                              float*        __restrict__ out_grad) {
    int warp_id = (blockIdx.x * blockDim.x + threadIdx.x) >> 5;
    int lane    = threadIdx.x & 31;
    if (warp_id >= NSEG) return;

    int lo  = g_start[warp_id];
    int hi  = g_start[warp_id + 1];
    int cnt = hi - lo;

    // prefetch up to 32 row ids (Poisson(5): cnt>32 essentially never)
    int rid = (lane < cnt) ? g_rows[lo + lane] : 0;

    float4 a0 = make_float4(0.f, 0.f, 0.f, 0.f);
    float4 a1 = a0, a2 = a0;

    int n32 = cnt < 32 ? cnt : 32;
    #pragma unroll 4
    for (int p = 0; p < n32; ++p) {
        long long row = __shfl_sync(0xffffffffu, rid, p);
        const float4* src = grad4 + row * ROW_F4;
        float4 v0 = __ldcs(src + lane);
        float4 v1 = __ldcs(src + lane + 32);
        float4 v2 = __ldcs(src + lane + 64);
        a0.x += v0.x; a0.y += v0.y; a0.z += v0.z; a0.w += v0.w;
        a1.x += v1.x; a1.y += v1.y; a1.z += v1.z; a1.w += v1.w;
        a2.x += v2.x; a2.y += v2.y; a2.z += v2.z; a2.w += v2.w;
    }
    for (int p = 32; p < cnt; ++p) {            // overflow fallback
        long long row = g_rows[lo + p];
        const float4* src = grad4 + row * ROW_F4;
        float4 v0 = __ldcs(src + lane);
        float4 v1 = __ldcs(src + lane + 32);
        float4 v2 = __ldcs(src + lane + 64);
        a0.x += v0.x; a0.y += v0.y; a0.z += v0.z; a0.w += v0.w;
        a1.x += v1.x; a1.y += v1.y; a1.z += v1.z; a1.w += v1.w;
        a2.x += v2.x; a2.y += v2.y; a2.z += v2.z; a2.w += v2.w;
    }

    float4* dst = (float4*)(out_grad + (long long)warp_id * (3 * DFEAT));
    dst[lane]      = a0;
    dst[lane + 32] = a1;
    dst[lane + 64] = a2;
}

// ---------------------------------------------------------------------------
extern "C" void kernel_launch(void* const* d_in, const int* in_sizes, int n_in,
                              void* d_out, int out_size) {
    const float*  values  = (const float*)d_in[0];
    const int*    sid     = (const int*)  d_in[1];
    const float4* grad4   = (const float4*)d_in[2];
    const int*    gstruct = (const int*)  d_in[3];
    const int*    gatom   = (const int*)  d_in[4];

    float* out      = (float*)d_out;
    float* out_grad = out + GRAD_OUT_OFFSET;

    zero_counts_kernel<<<(NSEG + 255) / 256, 256>>>();
    count_kernel<<<(N_GRAD + 255) / 256, 256>>>(gstruct, gatom);
    scan_p1<<<SCAN_NB, SCAN_TILE>>>();
    scan_p2<<<1, 128>>>();
    scan_p3<<<SCAN_NB, SCAN_TILE>>>();
    scatter_kernel<<<(N_GRAD + 255) / 256, 256>>>();

    values_kernel<<<N_STRUCT, DFEAT>>>(values, sid, out);

    {
        int threads = 256;
        int blocks  = (NSEG * 32 + threads - 1) / threads;
        gather_kernel<<<blocks, threads>>>(grad4, out_grad);
    }
}

// round 4
// speedup vs baseline: 1.8918x; 1.0781x over previous
#include <cuda_runtime.h>
#include <stdint.h>

#define N_STRUCT   1000
#define ATOMS      100
#define N_SAMP     100000
#define N_GRAD     500000
#define DFEAT      128
#define NSEG       (N_STRUCT * ATOMS)      // 100000
#define ROW_F4     96                      // 3*128/4
#define GRAD_OUT_OFFSET (N_STRUCT * DFEAT)

#define SCAN_TILE  1024
#define SCAN_NB    ((NSEG + SCAN_TILE - 1) / SCAN_TILE)   // 98

#define GATHER_BLOCKS (NSEG / 8)           // 12500 (8 warps/block, 1 seg/warp)
#define VALUES_BLOCKS (N_STRUCT / 2)       // 500   (2 structures per 256-thr block)

// -------- scratch (device globals; zero-initialized at module load) --------
__device__ int g_count[NSEG];     // invariant: all-zero at kernel_launch entry
__device__ int g_start[NSEG + 1];
__device__ int g_cursor[NSEG];
__device__ int g_rows[N_GRAD];
__device__ int g_seg[N_GRAD];
__device__ int g_bsum[SCAN_NB];

// ---------------------------------------------------------------------------
// count degrees + cache segment ids (g_count must be zero on entry; the
// gather kernel re-zeros it at the end of every launch sequence).
// ---------------------------------------------------------------------------
__global__ void count_kernel(const int* __restrict__ gstruct,
                             const int* __restrict__ gatom) {
    int i = blockIdx.x * blockDim.x + threadIdx.x;
    if (i < N_GRAD) {
        int seg = gstruct[i] * ATOMS + gatom[i];
        g_seg[i] = seg;
        atomicAdd(&g_count[seg], 1);
    }
}

// Phase 1: per-tile sums (coalesced)
__global__ void scan_p1() {
    __shared__ int sh[SCAN_TILE];
    int b = blockIdx.x;
    int i = b * SCAN_TILE + threadIdx.x;
    int v = (i < NSEG) ? g_count[i] : 0;
    sh[threadIdx.x] = v;
    __syncthreads();
    for (int off = SCAN_TILE / 2; off > 0; off >>= 1) {
        if (threadIdx.x < off) sh[threadIdx.x] += sh[threadIdx.x + off];
        __syncthreads();
    }
    if (threadIdx.x == 0) g_bsum[b] = sh[0];
}

// Phase 2+3 fused: each block computes its own exclusive block offset from
// g_bsum (98 ints), then tile-local scan; writes g_start/g_cursor.
__global__ void scan_p3() {
    __shared__ int sh[SCAN_TILE];
    __shared__ int s_boff;
    int b = blockIdx.x;
    int i = b * SCAN_TILE + threadIdx.x;

    // block offset: warp 0 reduces g_bsum[0..b)
    if (threadIdx.x < 32) {
        int acc = 0;
        for (int j = threadIdx.x; j < b; j += 32) acc += g_bsum[j];
        #pragma unroll
        for (int off = 16; off > 0; off >>= 1)
            acc += __shfl_down_sync(0xffffffffu, acc, off);
        if (threadIdx.x == 0) s_boff = acc;
    }

    int v = (i < NSEG) ? g_count[i] : 0;
    sh[threadIdx.x] = v;
    __syncthreads();
    // Hillis-Steele inclusive scan
    for (int off = 1; off < SCAN_TILE; off <<= 1) {
        int t = (threadIdx.x >= off) ? sh[threadIdx.x - off] : 0;
        __syncthreads();
        sh[threadIdx.x] += t;
        __syncthreads();
    }
    if (i < NSEG) {
        int excl = sh[threadIdx.x] - v + s_boff;
        g_start[i]  = excl;
        g_cursor[i] = excl;
    }
    if (i == NSEG - 1) g_start[NSEG] = N_GRAD;
}

__global__ void scatter_kernel() {
    int i = blockIdx.x * blockDim.x + threadIdx.x;
    if (i < N_GRAD) {
        int pos = atomicAdd(&g_cursor[g_seg[i]], 1);
        g_rows[pos] = i;
    }
}

// ---------------------------------------------------------------------------
// Fused mega-kernel:
//   blocks [0, GATHER_BLOCKS): gather-reduce, 1 warp per segment; also
//                              re-zeros g_count (restores the invariant).
//   blocks [GATHER_BLOCKS, +VALUES_BLOCKS): per-structure value sums
//                              (structure_ids sorted -> binary search).
// ---------------------------------------------------------------------------
__global__ void fused_kernel(const float4* __restrict__ grad4,
                             float*        __restrict__ out_grad,
                             const float*  __restrict__ values,
                             const int*    __restrict__ sid,
                             float*        __restrict__ out) {
    if (blockIdx.x < GATHER_BLOCKS) {
        // restore g_count == 0 invariant (cheap, overlapped)
        int zi = blockIdx.x * 256 + threadIdx.x;
        if (zi < NSEG) g_count[zi] = 0;

        int warp_id = (blockIdx.x * 256 + threadIdx.x) >> 5;
        int lane    = threadIdx.x & 31;

        int lo  = g_start[warp_id];
        int hi  = g_start[warp_id + 1];
        int cnt = hi - lo;

        // prefetch up to 32 row ids (Poisson(5): cnt>32 essentially never)
        int rid = (lane < cnt) ? g_rows[lo + lane] : 0;

        float4 a0 = make_float4(0.f, 0.f, 0.f, 0.f);
        float4 a1 = a0, a2 = a0;

        int n32 = cnt < 32 ? cnt : 32;
        #pragma unroll 4
        for (int p = 0; p < n32; ++p) {
            long long row = __shfl_sync(0xffffffffu, rid, p);
            const float4* src = grad4 + row * ROW_F4;
            float4 v0 = __ldcs(src + lane);
            float4 v1 = __ldcs(src + lane + 32);
            float4 v2 = __ldcs(src + lane + 64);
            a0.x += v0.x; a0.y += v0.y; a0.z += v0.z; a0.w += v0.w;
            a1.x += v1.x; a1.y += v1.y; a1.z += v1.z; a1.w += v1.w;
            a2.x += v2.x; a2.y += v2.y; a2.z += v2.z; a2.w += v2.w;
        }
        for (int p = 32; p < cnt; ++p) {    // overflow fallback
            long long row = g_rows[lo + p];
            const float4* src = grad4 + row * ROW_F4;
            float4 v0 = __ldcs(src + lane);
            float4 v1 = __ldcs(src + lane + 32);
            float4 v2 = __ldcs(src + lane + 64);
            a0.x += v0.x; a0.y += v0.y; a0.z += v0.z; a0.w += v0.w;
            a1.x += v1.x; a1.y += v1.y; a1.z += v1.z; a1.w += v1.w;
            a2.x += v2.x; a2.y += v2.y; a2.z += v2.z; a2.w += v2.w;
        }

        float4* dst = (float4*)(out_grad + (long long)warp_id * (3 * DFEAT));
        __stcs(dst + lane,      a0);
        __stcs(dst + lane + 32, a1);
        __stcs(dst + lane + 64, a2);
    } else {
        // values segment-sum: 2 structures per block (128 threads each)
        int vb   = blockIdx.x - GATHER_BLOCKS;
        int half = threadIdx.x >> 7;            // 0 or 1
        int d    = threadIdx.x & 127;
        int s    = vb * 2 + half;

        __shared__ int s_lo[2], s_hi[2];
        if (d == 0) {
            int lo = 0, hi = N_SAMP;
            while (lo < hi) { int m = (lo + hi) >> 1; if (sid[m] < s) lo = m + 1; else hi = m; }
            s_lo[half] = lo;
            lo = s_lo[half]; hi = N_SAMP;
            while (lo < hi) { int m = (lo + hi) >> 1; if (sid[m] < s + 1) lo = m + 1; else hi = m; }
            s_hi[half] = lo;
        }
        __syncthreads();

        float acc = 0.f;
        int lo = s_lo[half], hi = s_hi[half];
        for (int r = lo; r < hi; ++r)
            acc += values[(long long)r * DFEAT + d];
        __stcs(out + (long long)s * DFEAT + d, acc);
    }
}

// ---------------------------------------------------------------------------
extern "C" void kernel_launch(void* const* d_in, const int* in_sizes, int n_in,
                              void* d_out, int out_size) {
    const float*  values  = (const float*)d_in[0];
    const int*    sid     = (const int*)  d_in[1];
    const float4* grad4   = (const float4*)d_in[2];
    const int*    gstruct = (const int*)  d_in[3];
    const int*    gatom   = (const int*)  d_in[4];

    float* out      = (float*)d_out;
    float* out_grad = out + GRAD_OUT_OFFSET;

    count_kernel<<<(N_GRAD + 255) / 256, 256>>>(gstruct, gatom);
    scan_p1<<<SCAN_NB, SCAN_TILE>>>();
    scan_p3<<<SCAN_NB, SCAN_TILE>>>();
    scatter_kernel<<<(N_GRAD + 255) / 256, 256>>>();

    fused_kernel<<<GATHER_BLOCKS + VALUES_BLOCKS, 256>>>(
        grad4, out_grad, values, sid, out);
}